// round 15
// baseline (speedup 1.0000x reference)
#include <cuda_runtime.h>

#define Bq 32
#define Tq 512
#define Dq 128
#define Nq 1024
#define NOISE_C 0.001f
#define GRID_G 128
#define NBL 16         // batches per CTA
#define NCOL 16        // cols per CTA
#define NTHR 1024
#define NW 32          // warps per CTA

typedef unsigned long long ull;

// States double buffer: g_Sg[ph][bg][k][16] — 64B per k.
__device__ float g_Sg[2][2][Nq][NBL];
// Counters g_gc[bg][chunk][32]: 64k-chunk of batch-group bg; 4 producer CTAs each.
__device__ unsigned g_gc[2 * 16 * 32];

// out[:,0,:] = step0 ; pack states0 ; reset counters
__global__ void init_kernel(const float* __restrict__ states0,
                            const float* __restrict__ step0,
                            float* __restrict__ out) {
    int i = blockIdx.x * blockDim.x + threadIdx.x;  // 0 .. 32767
    int b = i >> 10;
    int n = i & 1023;
    out[(size_t)b * Tq * Nq + n] = step0[i];
    g_Sg[0][b >> 4][n][b & 15] = states0[i];
    if (i < 2 * 16 * 32) g_gc[i] = 0u;
}

struct RecurSmem {
    // Wv[w][j][h][kq][ch][4]: k = 32w+4j+kq, c = ch*8 + h*4 + cc.
    // Each warp LDS.128 hits 8 distinct 16B blocks within ONE 128B span -> 1 wf.
    float Wv[NW][8][2][4][2][4];  // 64 KB
    float red[NW][NBL][20];       // 41 KB  80B rows
    float xs_x[2][NBL][132];      // 16.9 KB  x tile, parity double-buffered
    float wt[NCOL][132];          // 8.4 KB  w_input slice (pre-scaled, transposed)
    float xr4[4][256];            // 4 KB   xin quarter-dot partials
};
#define RECUR_SMEM_BYTES ((int)sizeof(RecurSmem))

// Persistent recurrence: 128 CTAs x 1024 threads (8 warps/SMSP for latency hiding),
// square 16x16 tiles, conflict-free W LDS, fused input projection, per-warp gating.
// Warp w: k chunk [32w,32w+32). Lane (kq,bh,ch): 8k x 4b x 8c, acc 16 f32x2.
__global__ __launch_bounds__(NTHR, 1) void recur_kernel(const float* __restrict__ w_res,
                                                        const float* __restrict__ x,
                                                        const float* __restrict__ w_in,
                                                        const float* __restrict__ scale_p,
                                                        const float* __restrict__ noise,
                                                        float* __restrict__ out) {
    extern __shared__ RecurSmem sm[];
    const float4* x4 = (const float4*)x;

    const int tid = threadIdx.x;
    const int cta = blockIdx.x;
    const int bg = cta >> 6;          // 0..1
    const int cg = cta & 63;          // 0..63
    const int col0 = cg * NCOL;
    unsigned* own_cnt = &g_gc[(bg * 16 + (cg >> 2)) * 32];

    // W slice: Wv[w][j][h][kq][ch][cc] = w_res[32w+4j+kq][col0 + ch*8 + h*4 + cc]
    for (int i = tid; i < Nq * NCOL; i += NTHR) {
        int k = i >> 4, c = i & 15;
        int w = k >> 5, j = (k >> 2) & 7, kq = k & 3;
        int ch = c >> 3, h = (c >> 2) & 1, cc = c & 3;
        sm->Wv[w][j][h][kq][ch][cc] = w_res[(size_t)k * Nq + col0 + c];
    }
    // w_input slice, transposed + pre-scaled
    const float sc = *scale_p;
    for (int i = tid; i < Dq * NCOL; i += NTHR) {
        int d = i >> 4, c = i & 15;
        sm->wt[c][d] = w_in[(size_t)d * Nq + col0 + c] * sc;
    }
    // stage x(:, t=1, :) into parity buffer 1 (16 batches x 32 float4 = 512 threads)
    if (tid < 512) {
        int b = tid >> 5, d4 = tid & 31;
        float4 v = x4[((size_t)(bg * NBL + b) * Tq + 1) * 32 + d4];
        *(float4*)&sm->xs_x[1][b][d4 * 4] = v;
    }
    __syncthreads();

    const int warp = tid >> 5;
    const int lane = tid & 31;
    const int kq = lane >> 3;         // bits 3,4 -> butterfly xor 8,16
    const int bh = (lane >> 1) & 3;   // 4-batch group
    const int ch = lane & 1;          // 8-col half
    unsigned* my_cnt = &g_gc[(bg * 16 + (warp >> 1)) * 32];

    // epilogue mapping (first 256 threads): eb = tid&15, ec = tid>>4
    const bool epi = (tid < NBL * NCOL);
    const int eb = tid & 15;
    const int ec = (tid >> 4) & 15;
    const int gb = bg * NBL + eb;
    const int gc = col0 + ec;
    const float nz = NOISE_C * noise[gb * Nq + gc];
    float* outp = out + (size_t)gb * Tq * Nq + gc;
    float* sSt0 = &g_Sg[0][bg][gc][eb];
    float* sSt1 = &g_Sg[1][bg][gc][eb];

    // fused-xin quarter-dot mapping: hh = d-quarter (32 d), he = (heb, hec)
    const int he = tid & 255;
    const int hh = tid >> 8;          // 0..3
    const int heb = he & 15;
    const int hec = (he >> 4) & 15;

    // W lane base: &Wv[warp][0][0][kq][ch][0]; j stride 64 floats; h stride 32 floats
    const float* Wb = &sm->Wv[warp][0][0][kq][ch][0];
    // state float4 base: k*4 + bh, k = 32*warp + kq; j stride (4 k) = 16 float4
    const int ks0 = (warp * 32 + kq) * 4 + bh;

    for (int t = 1; t < Tq; ++t) {
        const int p = t & 1;

        // ---- fused xin: quarter-dot over d in [32*hh, 32*hh+32) ----
        {
            const float4* xp = (const float4*)&sm->xs_x[p][heb][hh * 32];
            const float4* wp4 = (const float4*)&sm->wt[hec][hh * 32];
            ull acc2 = 0;
#pragma unroll
            for (int j = 0; j < 8; ++j) {
                float4 xv = xp[j];
                float4 wv = wp4[j];
                ull x01 = ((const ull*)&xv)[0], x23 = ((const ull*)&xv)[1];
                ull w01 = ((const ull*)&wv)[0], w23 = ((const ull*)&wv)[1];
                asm("fma.rn.f32x2 %0, %1, %2, %0;" : "+l"(acc2) : "l"(x01), "l"(w01));
                asm("fma.rn.f32x2 %0, %1, %2, %0;" : "+l"(acc2) : "l"(x23), "l"(w23));
            }
            sm->xr4[hh][he] = __uint_as_float((unsigned)acc2) +
                              __uint_as_float((unsigned)(acc2 >> 32));
        }

        // ---- per-warp gate: wait for OUR chunk's 4 producers (prev step) ----
        const unsigned tgt = 4u * (unsigned)(t - 1);
        if (lane == 0) {
            unsigned v;
            do {
                asm volatile("ld.acquire.gpu.u32 %0, [%1];"
                             : "=r"(v) : "l"(my_cnt) : "memory");
                if (v < tgt) __nanosleep(8);
            } while (v < tgt);
        }
        __syncwarp();

        // ---- main FMA: 8 k steps, acc[4b][8c] as 16 f32x2, depth-2 prefetch ----
        const float4* Sp = (const float4*)g_Sg[(t - 1) & 1][bg] + ks0;
        float4 buf[2];
        buf[0] = __ldcg(Sp);
        buf[1] = __ldcg(Sp + 16);

        ull a[16];
#pragma unroll
        for (int m = 0; m < 16; ++m) a[m] = 0ull;

        const float* wp = Wb;
#pragma unroll
        for (int j = 0; j < 8; ++j) {
            float4 s = buf[j & 1];                    // 4 batches at k = 32w+4j+kq
            if (j < 6) buf[j & 1] = __ldcg(Sp + (j + 2) * 16);
            ulonglong2 u0 = *(const ulonglong2*)wp;        // cols ch*8+0..3
            ulonglong2 u1 = *(const ulonglong2*)(wp + 32); // cols ch*8+4..7
            wp += 64;                                      // next j
            ull sv0, sv1, sv2, sv3;
            asm("mov.b64 %0, {%1, %1};" : "=l"(sv0) : "r"(__float_as_uint(s.x)));
            asm("mov.b64 %0, {%1, %1};" : "=l"(sv1) : "r"(__float_as_uint(s.y)));
            asm("mov.b64 %0, {%1, %1};" : "=l"(sv2) : "r"(__float_as_uint(s.z)));
            asm("mov.b64 %0, {%1, %1};" : "=l"(sv3) : "r"(__float_as_uint(s.w)));
            asm("fma.rn.f32x2 %0, %1, %2, %0;" : "+l"(a[0])  : "l"(sv0), "l"(u0.x));
            asm("fma.rn.f32x2 %0, %1, %2, %0;" : "+l"(a[1])  : "l"(sv0), "l"(u0.y));
            asm("fma.rn.f32x2 %0, %1, %2, %0;" : "+l"(a[2])  : "l"(sv0), "l"(u1.x));
            asm("fma.rn.f32x2 %0, %1, %2, %0;" : "+l"(a[3])  : "l"(sv0), "l"(u1.y));
            asm("fma.rn.f32x2 %0, %1, %2, %0;" : "+l"(a[4])  : "l"(sv1), "l"(u0.x));
            asm("fma.rn.f32x2 %0, %1, %2, %0;" : "+l"(a[5])  : "l"(sv1), "l"(u0.y));
            asm("fma.rn.f32x2 %0, %1, %2, %0;" : "+l"(a[6])  : "l"(sv1), "l"(u1.x));
            asm("fma.rn.f32x2 %0, %1, %2, %0;" : "+l"(a[7])  : "l"(sv1), "l"(u1.y));
            asm("fma.rn.f32x2 %0, %1, %2, %0;" : "+l"(a[8])  : "l"(sv2), "l"(u0.x));
            asm("fma.rn.f32x2 %0, %1, %2, %0;" : "+l"(a[9])  : "l"(sv2), "l"(u0.y));
            asm("fma.rn.f32x2 %0, %1, %2, %0;" : "+l"(a[10]) : "l"(sv2), "l"(u1.x));
            asm("fma.rn.f32x2 %0, %1, %2, %0;" : "+l"(a[11]) : "l"(sv2), "l"(u1.y));
            asm("fma.rn.f32x2 %0, %1, %2, %0;" : "+l"(a[12]) : "l"(sv3), "l"(u0.x));
            asm("fma.rn.f32x2 %0, %1, %2, %0;" : "+l"(a[13]) : "l"(sv3), "l"(u0.y));
            asm("fma.rn.f32x2 %0, %1, %2, %0;" : "+l"(a[14]) : "l"(sv3), "l"(u1.x));
            asm("fma.rn.f32x2 %0, %1, %2, %0;" : "+l"(a[15]) : "l"(sv3), "l"(u1.y));
        }

        // ---- cross-kq butterfly (lanes ±8, ±16), packed f32x2 adds ----
#pragma unroll
        for (int m = 0; m < 16; ++m) {
            ull o = __shfl_xor_sync(0xffffffffu, a[m], 8);
            asm("add.rn.f32x2 %0, %0, %1;" : "+l"(a[m]) : "l"(o));
        }
#pragma unroll
        for (int m = 0; m < 16; ++m) {
            ull o = __shfl_xor_sync(0xffffffffu, a[m], 16);
            asm("add.rn.f32x2 %0, %0, %1;" : "+l"(a[m]) : "l"(o));
        }

        // ---- stage x(:, t+1, :) for next step (consumed after sync1) ----
        if (t + 1 < Tq && tid < 512) {
            int b = tid >> 5, d4 = tid & 31;
            float4 v = x4[((size_t)(bg * NBL + b) * Tq + (t + 1)) * 32 + d4];
            *(float4*)&sm->xs_x[p ^ 1][b][d4 * 4] = v;
        }

        if (kq == 0) {   // lanes 0-7 (bh,ch) hold warp-chunk sums for (4b x 8c)
#pragma unroll
            for (int i = 0; i < 4; ++i) {
                *(ulonglong2*)&sm->red[warp][bh * 4 + i][ch * 8] =
                    make_ulonglong2(a[i * 4 + 0], a[i * 4 + 1]);
                *(ulonglong2*)&sm->red[warp][bh * 4 + i][ch * 8 + 4] =
                    make_ulonglong2(a[i * 4 + 2], a[i * 4 + 3]);
            }
        }
        __syncthreads();   // sync1: red + xr4 + xs_x(t+1) all visible

        if (epi) {
            float xin = (sm->xr4[0][tid] + sm->xr4[1][tid]) +
                        (sm->xr4[2][tid] + sm->xr4[3][tid]);
            float sum = 0.f;
#pragma unroll
            for (int w = 0; w < NW; ++w) sum += sm->red[w][eb][ec];

            float post = tanhf(sum + xin) + nz;
            outp[(size_t)t * Nq] = post;        // only our own element — safe
            *((p) ? sSt1 : sSt0) = post;        // next-step state (read via __ldcg)
        }

        // ---- arrive at own gang counter (release publishes state writes) ----
        __syncthreads();   // sync2: epilogue reads done; state writes done; HB to t0
        if (tid == 0) {
            asm volatile("red.release.gpu.add.u32 [%0], %1;"
                         :: "l"(own_cnt), "r"(1u) : "memory");
        }
    }
}

extern "C" void kernel_launch(void* const* d_in, const int* in_sizes, int n_in,
                              void* d_out, int out_size) {
    (void)in_sizes; (void)n_in; (void)out_size;
    const float* x       = (const float*)d_in[0];
    const float* w_input = (const float*)d_in[1];
    const float* w_res   = (const float*)d_in[2];
    const float* w_scale = (const float*)d_in[3];
    const float* states0 = (const float*)d_in[4];
    const float* step0   = (const float*)d_in[5];
    const float* rnoise  = (const float*)d_in[6];
    float* out = (float*)d_out;

    cudaFuncSetAttribute(recur_kernel, cudaFuncAttributeMaxDynamicSharedMemorySize,
                         RECUR_SMEM_BYTES);

    init_kernel<<<128, 256>>>(states0, step0, out);
    recur_kernel<<<GRID_G, NTHR, RECUR_SMEM_BYTES>>>(w_res, x, w_input, w_scale,
                                                     rnoise, out);
}

// round 16
// speedup vs baseline: 1.3265x; 1.3265x over previous
#include <cuda_runtime.h>

#define Bq 32
#define Tq 512
#define Dq 128
#define Nq 1024
#define NOISE_C 0.001f
#define GRID_G 128
#define NBL 16         // batches per CTA
#define NCOL 16        // cols per CTA
#define NTHR 512
#define NW 16          // warps per CTA

typedef unsigned long long ull;

// States double buffer: g_Sg[ph][bg][k][16] — 64B per k.
__device__ float g_Sg[2][2][Nq][NBL];
// Counters g_gc[bg][chunk][32]: 64k-chunk of batch-group bg; 4 producer CTAs each.
__device__ unsigned g_gc[2 * 16 * 32];

// out[:,0,:] = step0 ; pack states0 ; reset counters
__global__ void init_kernel(const float* __restrict__ states0,
                            const float* __restrict__ step0,
                            float* __restrict__ out) {
    int i = blockIdx.x * blockDim.x + threadIdx.x;  // 0 .. 32767
    int b = i >> 10;
    int n = i & 1023;
    out[(size_t)b * Tq * Nq + n] = step0[i];
    g_Sg[0][b >> 4][n][b & 15] = states0[i];
    if (i < 2 * 16 * 32) g_gc[i] = 0u;
}

struct RecurSmem {
    // Wv[w][j][h][kq][ch][cc]: k = 64w+4j+kq, c = ch*8 + h*4 + cc.
    // Warp LDS.128 (fixed h) hits 8 distinct 16B blocks within ONE 128B span -> 1 wf.
    float Wv[NW][16][2][4][2][4]; // 64 KB
    float red[NW][NBL][20];       // 20.5 KB  80B rows
    float xs_x[2][NBL][132];      // 16.9 KB  x tile, parity double-buffered
    float wt[NCOL][132];          // 8.4 KB  w_input slice (pre-scaled, transposed)
    float xr2[2][256];            // 2 KB   xin half-dot partials
};
#define RECUR_SMEM_BYTES ((int)sizeof(RecurSmem))

// Persistent recurrence (R14 1735us winner + conflict-free W LDS, single change).
// 128 CTAs = 2 bg x 64 cg, 512 threads. Warp w: k chunk [64w,64w+64).
// Lane (kq,bh,ch): 16k x 4b x 8c, acc = 16 f32x2; butterfly over kq.
__global__ __launch_bounds__(NTHR, 1) void recur_kernel(const float* __restrict__ w_res,
                                                        const float* __restrict__ x,
                                                        const float* __restrict__ w_in,
                                                        const float* __restrict__ scale_p,
                                                        const float* __restrict__ noise,
                                                        float* __restrict__ out) {
    extern __shared__ RecurSmem sm[];
    const float4* x4 = (const float4*)x;

    const int tid = threadIdx.x;
    const int cta = blockIdx.x;
    const int bg = cta >> 6;          // 0..1
    const int cg = cta & 63;          // 0..63
    const int col0 = cg * NCOL;
    unsigned* own_cnt = &g_gc[(bg * 16 + (cg >> 2)) * 32];

    // W slice: Wv[w][j][h][kq][ch][cc] = w_res[64w+4j+kq][col0 + ch*8 + h*4 + cc]
    for (int i = tid; i < Nq * NCOL; i += NTHR) {
        int k = i >> 4, c = i & 15;
        int w = k >> 6, j = (k >> 2) & 15, kq = k & 3;
        int ch = c >> 3, h = (c >> 2) & 1, cc = c & 3;
        sm->Wv[w][j][h][kq][ch][cc] = w_res[(size_t)k * Nq + col0 + c];
    }
    // w_input slice, transposed + pre-scaled
    const float sc = *scale_p;
    for (int i = tid; i < Dq * NCOL; i += NTHR) {
        int d = i >> 4, c = i & 15;
        sm->wt[c][d] = w_in[(size_t)d * Nq + col0 + c] * sc;
    }
    // stage x(:, t=1, :) into parity buffer 1 (16 batches x 32 float4 = 512)
    {
        int b = tid >> 5, d4 = tid & 31;
        float4 v = x4[((size_t)(bg * NBL + b) * Tq + 1) * 32 + d4];
        *(float4*)&sm->xs_x[1][b][d4 * 4] = v;
    }
    __syncthreads();

    const int warp = tid >> 5;
    const int lane = tid & 31;
    const int kq = lane >> 3;         // bits 3,4 -> butterfly xor 8,16
    const int bh = (lane >> 1) & 3;   // 4-batch group
    const int ch = lane & 1;          // 8-col half
    unsigned* my_cnt = &g_gc[(bg * 16 + warp) * 32];

    // epilogue mapping (first 256 threads): eb = tid&15, ec = tid>>4
    const bool epi = (tid < NBL * NCOL);
    const int eb = tid & 15;
    const int ec = (tid >> 4) & 15;
    const int gb = bg * NBL + eb;
    const int gc = col0 + ec;
    const float nz = NOISE_C * noise[gb * Nq + gc];
    float* outp = out + (size_t)gb * Tq * Nq + gc;
    float* sSt0 = &g_Sg[0][bg][gc][eb];
    float* sSt1 = &g_Sg[1][bg][gc][eb];

    // fused-xin half-dot mapping (all 512 threads): he=(heb,hec), hh = d-half
    const int he = tid & 255;
    const int hh = tid >> 8;
    const int heb = he & 15;
    const int hec = (he >> 4) & 15;

    // W lane base: &Wv[warp][0][0][kq][ch][0]; j stride = 64 floats; h stride = 32
    const float* Wb = &sm->Wv[warp][0][0][kq][ch][0];
    // state float4 base index into g_Sg[ph][bg]: (64*warp+kq)*4 + bh; j stride 16
    const int ks0 = (warp * 64 + kq) * 4 + bh;

    for (int t = 1; t < Tq; ++t) {
        const int p = t & 1;

        // ---- fused xin: half-dot over d in [64*hh, 64*hh+64) (gate-independent) ----
        {
            const float4* xp = (const float4*)&sm->xs_x[p][heb][hh * 64];
            const float4* wp4 = (const float4*)&sm->wt[hec][hh * 64];
            ull acc2 = 0;
#pragma unroll
            for (int j = 0; j < 16; ++j) {
                float4 xv = xp[j];
                float4 wv = wp4[j];
                ull x01 = ((const ull*)&xv)[0], x23 = ((const ull*)&xv)[1];
                ull w01 = ((const ull*)&wv)[0], w23 = ((const ull*)&wv)[1];
                asm("fma.rn.f32x2 %0, %1, %2, %0;" : "+l"(acc2) : "l"(x01), "l"(w01));
                asm("fma.rn.f32x2 %0, %1, %2, %0;" : "+l"(acc2) : "l"(x23), "l"(w23));
            }
            sm->xr2[hh][he] = __uint_as_float((unsigned)acc2) +
                              __uint_as_float((unsigned)(acc2 >> 32));
        }

        // ---- per-warp gate: wait for OUR chunk's 4 producers (prev step) ----
        const unsigned tgt = 4u * (unsigned)(t - 1);
        if (lane == 0) {
            unsigned v;
            do {
                asm volatile("ld.acquire.gpu.u32 %0, [%1];"
                             : "=r"(v) : "l"(my_cnt) : "memory");
                if (v < tgt) __nanosleep(8);
            } while (v < tgt);
        }
        __syncwarp();

        // ---- main FMA: 16 k steps, acc[4b][8c] as 16 f32x2 ----
        const float4* Sp = (const float4*)g_Sg[(t - 1) & 1][bg] + ks0;
        float4 buf[8];
#pragma unroll
        for (int j = 0; j < 8; ++j) buf[j] = __ldcg(Sp + j * 16);

        ull a[16];
#pragma unroll
        for (int m = 0; m < 16; ++m) a[m] = 0ull;

        const float* wp = Wb;
#pragma unroll
        for (int j = 0; j < 16; ++j) {
            float4 s = buf[j & 7];                    // 4 batches at k = 64w+4j+kq
            if (j < 8) buf[j & 7] = __ldcg(Sp + (j + 8) * 16);
            ulonglong2 u0 = *(const ulonglong2*)wp;        // cols ch*8+0..3 (h=0)
            ulonglong2 u1 = *(const ulonglong2*)(wp + 32); // cols ch*8+4..7 (h=1)
            wp += 64;                                      // next j
            ull sv0, sv1, sv2, sv3;
            asm("mov.b64 %0, {%1, %1};" : "=l"(sv0) : "r"(__float_as_uint(s.x)));
            asm("mov.b64 %0, {%1, %1};" : "=l"(sv1) : "r"(__float_as_uint(s.y)));
            asm("mov.b64 %0, {%1, %1};" : "=l"(sv2) : "r"(__float_as_uint(s.z)));
            asm("mov.b64 %0, {%1, %1};" : "=l"(sv3) : "r"(__float_as_uint(s.w)));
            asm("fma.rn.f32x2 %0, %1, %2, %0;" : "+l"(a[0])  : "l"(sv0), "l"(u0.x));
            asm("fma.rn.f32x2 %0, %1, %2, %0;" : "+l"(a[1])  : "l"(sv0), "l"(u0.y));
            asm("fma.rn.f32x2 %0, %1, %2, %0;" : "+l"(a[2])  : "l"(sv0), "l"(u1.x));
            asm("fma.rn.f32x2 %0, %1, %2, %0;" : "+l"(a[3])  : "l"(sv0), "l"(u1.y));
            asm("fma.rn.f32x2 %0, %1, %2, %0;" : "+l"(a[4])  : "l"(sv1), "l"(u0.x));
            asm("fma.rn.f32x2 %0, %1, %2, %0;" : "+l"(a[5])  : "l"(sv1), "l"(u0.y));
            asm("fma.rn.f32x2 %0, %1, %2, %0;" : "+l"(a[6])  : "l"(sv1), "l"(u1.x));
            asm("fma.rn.f32x2 %0, %1, %2, %0;" : "+l"(a[7])  : "l"(sv1), "l"(u1.y));
            asm("fma.rn.f32x2 %0, %1, %2, %0;" : "+l"(a[8])  : "l"(sv2), "l"(u0.x));
            asm("fma.rn.f32x2 %0, %1, %2, %0;" : "+l"(a[9])  : "l"(sv2), "l"(u0.y));
            asm("fma.rn.f32x2 %0, %1, %2, %0;" : "+l"(a[10]) : "l"(sv2), "l"(u1.x));
            asm("fma.rn.f32x2 %0, %1, %2, %0;" : "+l"(a[11]) : "l"(sv2), "l"(u1.y));
            asm("fma.rn.f32x2 %0, %1, %2, %0;" : "+l"(a[12]) : "l"(sv3), "l"(u0.x));
            asm("fma.rn.f32x2 %0, %1, %2, %0;" : "+l"(a[13]) : "l"(sv3), "l"(u0.y));
            asm("fma.rn.f32x2 %0, %1, %2, %0;" : "+l"(a[14]) : "l"(sv3), "l"(u1.x));
            asm("fma.rn.f32x2 %0, %1, %2, %0;" : "+l"(a[15]) : "l"(sv3), "l"(u1.y));
        }

        // ---- cross-kq butterfly (lanes ±8, ±16), packed f32x2 adds ----
#pragma unroll
        for (int m = 0; m < 16; ++m) {
            ull o = __shfl_xor_sync(0xffffffffu, a[m], 8);
            asm("add.rn.f32x2 %0, %0, %1;" : "+l"(a[m]) : "l"(o));
        }
#pragma unroll
        for (int m = 0; m < 16; ++m) {
            ull o = __shfl_xor_sync(0xffffffffu, a[m], 16);
            asm("add.rn.f32x2 %0, %0, %1;" : "+l"(a[m]) : "l"(o));
        }

        // ---- stage x(:, t+1, :) for next step (consumed after sync1) ----
        if (t + 1 < Tq) {
            int b = tid >> 5, d4 = tid & 31;
            float4 v = x4[((size_t)(bg * NBL + b) * Tq + (t + 1)) * 32 + d4];
            *(float4*)&sm->xs_x[p ^ 1][b][d4 * 4] = v;
        }

        if (kq == 0) {   // lanes 0-7 (bh,ch) hold warp-chunk sums for (4b x 8c)
#pragma unroll
            for (int i = 0; i < 4; ++i) {
                *(ulonglong2*)&sm->red[warp][bh * 4 + i][ch * 8] =
                    make_ulonglong2(a[i * 4 + 0], a[i * 4 + 1]);
                *(ulonglong2*)&sm->red[warp][bh * 4 + i][ch * 8 + 4] =
                    make_ulonglong2(a[i * 4 + 2], a[i * 4 + 3]);
            }
        }
        __syncthreads();   // sync1: red + xr2 + xs_x(t+1) all visible

        if (epi) {
            float xin = sm->xr2[0][tid] + sm->xr2[1][tid];
            float sum = 0.f;
#pragma unroll
            for (int w = 0; w < NW; ++w) sum += sm->red[w][eb][ec];

            float post = tanhf(sum + xin) + nz;
            outp[(size_t)t * Nq] = post;        // only our own element — safe
            *((p) ? sSt1 : sSt0) = post;        // next-step state (read via __ldcg)
        }

        // ---- arrive at own gang counter (release publishes state writes) ----
        __syncthreads();   // sync2: epilogue reads done; state writes done; HB to t0
        if (tid == 0) {
            asm volatile("red.release.gpu.add.u32 [%0], %1;"
                         :: "l"(own_cnt), "r"(1u) : "memory");
        }
    }
}

extern "C" void kernel_launch(void* const* d_in, const int* in_sizes, int n_in,
                              void* d_out, int out_size) {
    (void)in_sizes; (void)n_in; (void)out_size;
    const float* x       = (const float*)d_in[0];
    const float* w_input = (const float*)d_in[1];
    const float* w_res   = (const float*)d_in[2];
    const float* w_scale = (const float*)d_in[3];
    const float* states0 = (const float*)d_in[4];
    const float* step0   = (const float*)d_in[5];
    const float* rnoise  = (const float*)d_in[6];
    float* out = (float*)d_out;

    cudaFuncSetAttribute(recur_kernel, cudaFuncAttributeMaxDynamicSharedMemorySize,
                         RECUR_SMEM_BYTES);

    init_kernel<<<128, 256>>>(states0, step0, out);
    recur_kernel<<<GRID_G, NTHR, RECUR_SMEM_BYTES>>>(w_res, x, w_input, w_scale,
                                                     rnoise, out);
}